// round 2
// baseline (speedup 1.0000x reference)
#include <cuda_runtime.h>
#include <cuda_bf16.h>

#define NTOK 49
#define DIMC 256
#define NH   8
#define HD   32
#define QKV_STRIDE 772     // 768 + 4 pad (stride%32==4 -> reduces k-preload conflicts)
#define XT_STRIDE  50      // 49 + 1 zero pad row, even for LDS.64 alignment
#define NPAIR 25           // 50/2 row pairs
#define ATT_SCALE 0.17677669529663687f   // 32^-0.5

// smem layout (floats):
//   xT  [256][50]   @ 0        (reused as O_T [256][50] after attention)
//   qkv [49][772]   @ 12800
//   ps  [8][52]     @ 50628
#define SM_XT   0
#define SM_QKV  12800
#define SM_PS   50628
#define SM_FLOATS (SM_PS + 8*52)          // 51044
#define SM_BYTES  (SM_FLOATS * 4)          // 204176

__device__ __forceinline__ unsigned long long pack2(float v) {
    unsigned long long r;
    unsigned u = __float_as_uint(v);
    asm("mov.b64 %0, {%1, %1};" : "=l"(r) : "r"(u));
    return r;
}
__device__ __forceinline__ void fma2(unsigned long long& acc,
                                     unsigned long long a,
                                     unsigned long long b) {
    asm("fma.rn.f32x2 %0, %1, %2, %3;" : "=l"(acc) : "l"(a), "l"(b), "l"(acc));
}
__device__ __forceinline__ void unpack2(unsigned long long v, float& lo, float& hi) {
    unsigned a, b;
    asm("mov.b64 {%0, %1}, %2;" : "=r"(a), "=r"(b) : "l"(v));
    lo = __uint_as_float(a);
    hi = __uint_as_float(b);
}

__global__ __launch_bounds__(256, 1)
void win_attn_fused_kernel(
    const float* __restrict__ x,          // [B, 49, 256]
    const float* __restrict__ mask,       // [nW, 49, 49]
    const float* __restrict__ qkv_w,      // [256, 768]
    const float* __restrict__ qkv_b,      // [768]
    const float* __restrict__ proj_w,     // [256, 256]
    const float* __restrict__ proj_b,     // [256]
    const float* __restrict__ bias_table, // [169, 8]
    const int*   __restrict__ rel_index,  // [49, 49]
    float*       __restrict__ out,        // [B, 49, 256]
    int nW)
{
    extern __shared__ float smem[];
    float* xT  = smem + SM_XT;    // [256][50], transposed x (k-major)
    float* qkv = smem + SM_QKV;   // [49][772]
    float* ps  = smem + SM_PS;    // [8][52] softmax rows per head

    const int b   = blockIdx.x;
    const int tid = threadIdx.x;

    // ---- Phase 1: load x transposed into smem, zero pad row 49 ----
    const float* xb = x + (size_t)b * NTOK * DIMC;
    for (int idx = tid; idx < NTOK * DIMC; idx += 256) {
        int n = idx >> 8;          // /256
        int k = idx & 255;
        xT[k * XT_STRIDE + n] = xb[idx];
    }
    xT[tid * XT_STRIDE + 49] = 0.0f;   // pad row so row-pairs cover 50 rows
    __syncthreads();

    // ---- Phase 2: QKV GEMM: qkv[n][j] = sum_k x[n][k]*W[k][j] + b[j] ----
    // 3 column passes: j = c*256 + tid. f32x2 packs rows (2i, 2i+1).
    #pragma unroll 1
    for (int c = 0; c < 3; c++) {
        const int j = c * DIMC + tid;
        unsigned long long acc[NPAIR];
        #pragma unroll
        for (int i = 0; i < NPAIR; i++) acc[i] = 0ull;
        const float* wcol = qkv_w + j;
        #pragma unroll 4
        for (int k = 0; k < DIMC; k++) {
            unsigned long long w2 = pack2(__ldg(wcol + k * 768));
            const unsigned long long* xr =
                (const unsigned long long*)(xT + k * XT_STRIDE);
            #pragma unroll
            for (int i = 0; i < NPAIR; i++) fma2(acc[i], xr[i], w2);
        }
        const float bj = __ldg(qkv_b + j);
        const float sc = (c == 0) ? ATT_SCALE : 1.0f;  // fold score scale into q
        #pragma unroll
        for (int i = 0; i < NPAIR; i++) {
            float lo, hi;
            unpack2(acc[i], lo, hi);
            qkv[(2 * i) * QKV_STRIDE + j] = (lo + bj) * sc;
            if (2 * i + 1 < NTOK)
                qkv[(2 * i + 1) * QKV_STRIDE + j] = (hi + bj) * sc;
        }
    }
    __syncthreads();

    // ---- Phase 3: attention. One warp per head. ----
    {
        const int h    = tid >> 5;
        const int lane = tid & 31;

        // k fragments in registers: chunk A m=lane (0..31), chunk B m=lane+32 (32..48)
        float kA[HD], kB[HD], vr[NTOK];
        {
            const float4* kp =
                (const float4*)(qkv + lane * QKV_STRIDE + DIMC + h * HD);
            #pragma unroll
            for (int i = 0; i < 8; i++) {
                float4 t = kp[i];
                kA[4*i] = t.x; kA[4*i+1] = t.y; kA[4*i+2] = t.z; kA[4*i+3] = t.w;
            }
        }
        if (lane < 17) {
            const float4* kp =
                (const float4*)(qkv + (lane + 32) * QKV_STRIDE + DIMC + h * HD);
            #pragma unroll
            for (int i = 0; i < 8; i++) {
                float4 t = kp[i];
                kB[4*i] = t.x; kB[4*i+1] = t.y; kB[4*i+2] = t.z; kB[4*i+3] = t.w;
            }
        } else {
            #pragma unroll
            for (int i = 0; i < HD; i++) kB[i] = 0.0f;
        }
        // v fragment: lane owns head-dim d=lane, all 49 rows
        #pragma unroll
        for (int m = 0; m < NTOK; m++)
            vr[m] = qkv[m * QKV_STRIDE + 2 * DIMC + h * HD + lane];

        const float* maskw = mask + (size_t)(b % nW) * NTOK * NTOK;
        float* O   = xT;          // reuse as O_T [256][50]; pad col 49 stays 0
        float* psh = ps + h * 52;

        #pragma unroll 1
        for (int n = 0; n < NTOK; n++) {
            float sA = 0.0f, sB = 0.0f;
            const float* qrow = qkv + n * QKV_STRIDE + h * HD;  // q (scaled)
            #pragma unroll
            for (int d = 0; d < HD; d++) {
                float qd = qrow[d];      // broadcast LDS
                sA = fmaf(qd, kA[d], sA);
                sB = fmaf(qd, kB[d], sB);
            }
            // relative position bias + window mask
            {
                int ri = __ldg(rel_index + n * NTOK + lane);
                sA += __ldg(bias_table + ri * NH + h)
                    + __ldg(maskw + n * NTOK + lane);
            }
            if (lane < 17) {
                int ri = __ldg(rel_index + n * NTOK + 32 + lane);
                sB += __ldg(bias_table + ri * NH + h)
                    + __ldg(maskw + n * NTOK + 32 + lane);
            }
            // softmax over 49 values held in lanes
            float mx = (lane < 17) ? fmaxf(sA, sB) : sA;
            #pragma unroll
            for (int o = 16; o > 0; o >>= 1)
                mx = fmaxf(mx, __shfl_xor_sync(0xffffffffu, mx, o));
            float eA = __expf(sA - mx);
            float eB = (lane < 17) ? __expf(sB - mx) : 0.0f;
            float sm = eA + eB;
            #pragma unroll
            for (int o = 16; o > 0; o >>= 1)
                sm += __shfl_xor_sync(0xffffffffu, sm, o);
            float r = 1.0f / sm;
            psh[lane] = eA * r;
            if (lane < 17) psh[32 + lane] = eB * r;
            __syncwarp();
            // P @ V: lane owns head-dim d=lane
            float acc = 0.0f;
            #pragma unroll
            for (int m = 0; m < NTOK; m++)
                acc = fmaf(psh[m], vr[m], acc);   // broadcast LDS * reg
            O[(h * HD + lane) * XT_STRIDE + n] = acc;
            __syncwarp();   // protect psh for next row
        }
    }
    __syncthreads();

    // ---- Phase 4: proj GEMM: out[n][j] = sum_k O[n][k]*Pw[k][j] + Pb[j] ----
    {
        const int j = tid;
        unsigned long long acc[NPAIR];
        #pragma unroll
        for (int i = 0; i < NPAIR; i++) acc[i] = 0ull;
        const float* wcol = proj_w + j;
        const float* O = xT;  // O_T [256][50], col 49 zero
        #pragma unroll 4
        for (int k = 0; k < DIMC; k++) {
            unsigned long long w2 = pack2(__ldg(wcol + k * DIMC));
            const unsigned long long* orow =
                (const unsigned long long*)(O + k * XT_STRIDE);
            #pragma unroll
            for (int i = 0; i < NPAIR; i++) fma2(acc[i], orow[i], w2);
        }
        const float pb = __ldg(proj_b + j);
        float* ob = out + (size_t)b * NTOK * DIMC + j;
        #pragma unroll
        for (int i = 0; i < NPAIR; i++) {
            float lo, hi;
            unpack2(acc[i], lo, hi);
            ob[(2 * i) * DIMC] = lo + pb;
            if (2 * i + 1 < NTOK)
                ob[(2 * i + 1) * DIMC] = hi + pb;
        }
    }
}

extern "C" void kernel_launch(void* const* d_in, const int* in_sizes, int n_in,
                              void* d_out, int out_size) {
    const float* x          = (const float*)d_in[0];
    const float* mask       = (const float*)d_in[1];
    const float* qkv_w      = (const float*)d_in[2];
    const float* qkv_b      = (const float*)d_in[3];
    const float* proj_w     = (const float*)d_in[4];
    const float* proj_b     = (const float*)d_in[5];
    const float* bias_table = (const float*)d_in[6];
    const int*   rel_index  = (const int*)d_in[7];
    float* out = (float*)d_out;

    const int B  = in_sizes[0] / (NTOK * DIMC);     // 2048
    const int nW = in_sizes[1] / (NTOK * NTOK);     // 64

    cudaFuncSetAttribute(win_attn_fused_kernel,
                         cudaFuncAttributeMaxDynamicSharedMemorySize, SM_BYTES);
    win_attn_fused_kernel<<<B, 256, SM_BYTES>>>(
        x, mask, qkv_w, qkv_b, proj_w, proj_b, bias_table, rel_index, out, nW);
}

// round 3
// speedup vs baseline: 1.0522x; 1.0522x over previous
#include <cuda_runtime.h>
#include <cuda_bf16.h>

#define NTOK 49
#define DIMC 256
#define NH   8
#define HD   32
#define QKV_STRIDE 772     // 768 + 4 pad
#define XT_STRIDE  50      // 49 + zero pad row
#define NPAIR 25
#define ATT_SCALE 0.17677669529663687f   // 32^-0.5

// smem layout (floats):
//   xT  [256][50]    @ 0        (reused as O_T [256][50] after attention)
//   qkv [49][772]    @ 12800
//   ps  [8][2][52]   @ 50628    (double-buffered softmax rows per head)
#define SM_XT   0
#define SM_QKV  12800
#define SM_PS   50628
#define SM_FLOATS (SM_PS + 8*104)          // 51460
#define SM_BYTES  (SM_FLOATS * 4)          // 205840

typedef unsigned long long u64;

__device__ __forceinline__ u64 pack2(float v) {
    u64 r; unsigned u = __float_as_uint(v);
    asm("mov.b64 %0, {%1, %1};" : "=l"(r) : "r"(u));
    return r;
}
__device__ __forceinline__ u64 pack_pair(float lo, float hi) {
    u64 r;
    asm("mov.b64 %0, {%1, %2};" : "=l"(r)
        : "r"(__float_as_uint(lo)), "r"(__float_as_uint(hi)));
    return r;
}
__device__ __forceinline__ void fma2(u64& acc, u64 a, u64 b) {
    asm("fma.rn.f32x2 %0, %1, %2, %3;" : "=l"(acc) : "l"(a), "l"(b), "l"(acc));
}
__device__ __forceinline__ void unpack2(u64 v, float& lo, float& hi) {
    unsigned a, b;
    asm("mov.b64 {%0, %1}, %2;" : "=r"(a), "=r"(b) : "l"(v));
    lo = __uint_as_float(a); hi = __uint_as_float(b);
}

// Proj partial: NP row-pairs starting at pair I0, 4 columns per thread.
template<int I0, int NP>
__device__ __forceinline__ void proj_part(
    const float* __restrict__ O, const float* __restrict__ proj_w,
    const float* __restrict__ proj_b, float* __restrict__ ob, int cg)
{
    u64 acc[4][NP];
    #pragma unroll
    for (int t = 0; t < 4; t++)
        #pragma unroll
        for (int i = 0; i < NP; i++) acc[t][i] = 0ull;

    float cw[4];
    #pragma unroll
    for (int t = 0; t < 4; t++) cw[t] = __ldg(proj_w + cg + t * 64);

    #pragma unroll 1
    for (int k = 0; k < DIMC; k++) {
        int kn = (k + 1 < DIMC) ? (k + 1) : (DIMC - 1);
        float nx[4];
        #pragma unroll
        for (int t = 0; t < 4; t++)
            nx[t] = __ldg(proj_w + kn * DIMC + cg + t * 64);
        u64 w2[4];
        #pragma unroll
        for (int t = 0; t < 4; t++) w2[t] = pack2(cw[t]);
        const u64* orow = (const u64*)(O + k * XT_STRIDE) + I0;
        #pragma unroll
        for (int i = 0; i < NP; i++) {
            u64 ov = orow[i];
            #pragma unroll
            for (int t = 0; t < 4; t++) fma2(acc[t][i], ov, w2[t]);
        }
        #pragma unroll
        for (int t = 0; t < 4; t++) cw[t] = nx[t];
    }
    #pragma unroll
    for (int t = 0; t < 4; t++) {
        int j = cg + t * 64;
        float pb = __ldg(proj_b + j);
        #pragma unroll
        for (int i = 0; i < NP; i++) {
            float lo, hi; unpack2(acc[t][i], lo, hi);
            int row = 2 * (I0 + i);
            ob[row * DIMC + j] = lo + pb;
            if (row + 1 < NTOK) ob[(row + 1) * DIMC + j] = hi + pb;
        }
    }
}

__global__ __launch_bounds__(256, 1)
void win_attn_fused_kernel(
    const float* __restrict__ x,          // [B, 49, 256]
    const float* __restrict__ mask,       // [nW, 49, 49]
    const float* __restrict__ qkv_w,      // [256, 768]
    const float* __restrict__ qkv_b,      // [768]
    const float* __restrict__ proj_w,     // [256, 256]
    const float* __restrict__ proj_b,     // [256]
    const float* __restrict__ bias_table, // [169, 8]
    const int*   __restrict__ rel_index,  // [49, 49]
    float*       __restrict__ out,        // [B, 49, 256]
    int nW)
{
    extern __shared__ float smem[];
    float* xT  = smem + SM_XT;    // [256][50]
    float* qkv = smem + SM_QKV;   // [49][772]
    float* ps  = smem + SM_PS;    // [8][2][52]

    const int b   = blockIdx.x;
    const int tid = threadIdx.x;

    // ---- Phase 1: load x transposed, zero pad row ----
    const float* xb = x + (size_t)b * NTOK * DIMC;
    for (int idx = tid; idx < NTOK * DIMC; idx += 256) {
        int n = idx >> 8;
        int k = idx & 255;
        xT[k * XT_STRIDE + n] = xb[idx];
    }
    xT[tid * XT_STRIDE + 49] = 0.0f;
    __syncthreads();

    // ---- Phase 2: QKV GEMM, single pass, 3 cols/thread ----
    {
        const int j0 = tid, j1 = tid + 256, j2 = tid + 512;
        u64 a0[NPAIR], a1[NPAIR], a2[NPAIR];
        #pragma unroll
        for (int i = 0; i < NPAIR; i++) { a0[i] = 0ull; a1[i] = 0ull; a2[i] = 0ull; }

        float c0 = __ldg(qkv_w + j0), c1 = __ldg(qkv_w + j1), c2 = __ldg(qkv_w + j2);
        #pragma unroll 1
        for (int k = 0; k < DIMC; k++) {
            int kn = (k + 1 < DIMC) ? (k + 1) : (DIMC - 1);
            const float* wr = qkv_w + kn * 768;
            float n0 = __ldg(wr + j0), n1 = __ldg(wr + j1), n2 = __ldg(wr + j2);
            u64 w0 = pack2(c0), w1 = pack2(c1), w2 = pack2(c2);
            const u64* xr = (const u64*)(xT + k * XT_STRIDE);
            #pragma unroll
            for (int i = 0; i < NPAIR; i++) {
                u64 xv = xr[i];
                fma2(a0[i], xv, w0);
                fma2(a1[i], xv, w1);
                fma2(a2[i], xv, w2);
            }
            c0 = n0; c1 = n1; c2 = n2;
        }
        // epilogue: bias; fold score scale into q (cols 0..255)
        float b0 = __ldg(qkv_b + j0), b1 = __ldg(qkv_b + j1), b2 = __ldg(qkv_b + j2);
        #pragma unroll
        for (int i = 0; i < NPAIR; i++) {
            float lo, hi;
            unpack2(a0[i], lo, hi);
            qkv[(2 * i) * QKV_STRIDE + j0] = (lo + b0) * ATT_SCALE;
            if (2 * i + 1 < NTOK)
                qkv[(2 * i + 1) * QKV_STRIDE + j0] = (hi + b0) * ATT_SCALE;
            unpack2(a1[i], lo, hi);
            qkv[(2 * i) * QKV_STRIDE + j1] = lo + b1;
            if (2 * i + 1 < NTOK)
                qkv[(2 * i + 1) * QKV_STRIDE + j1] = hi + b1;
            unpack2(a2[i], lo, hi);
            qkv[(2 * i) * QKV_STRIDE + j2] = lo + b2;
            if (2 * i + 1 < NTOK)
                qkv[(2 * i + 1) * QKV_STRIDE + j2] = hi + b2;
        }
    }
    __syncthreads();

    // ---- Phase 3: attention, one warp per head ----
    {
        const int h    = tid >> 5;
        const int lane = tid & 31;

        float kA[HD], kB[HD];
        {
            const float4* kp = (const float4*)(qkv + lane * QKV_STRIDE + DIMC + h * HD);
            #pragma unroll
            for (int i = 0; i < 8; i++) {
                float4 t = kp[i];
                kA[4*i] = t.x; kA[4*i+1] = t.y; kA[4*i+2] = t.z; kA[4*i+3] = t.w;
            }
        }
        if (lane < 17) {
            const float4* kp = (const float4*)(qkv + (lane + 32) * QKV_STRIDE + DIMC + h * HD);
            #pragma unroll
            for (int i = 0; i < 8; i++) {
                float4 t = kp[i];
                kB[4*i] = t.x; kB[4*i+1] = t.y; kB[4*i+2] = t.z; kB[4*i+3] = t.w;
            }
        } else {
            #pragma unroll
            for (int i = 0; i < HD; i++) kB[i] = 0.0f;
        }
        // v fragment packed as row-pairs: lane owns head-dim d=lane
        u64 v2[24]; float v48;
        {
            float vr[NTOK];
            #pragma unroll
            for (int m = 0; m < NTOK; m++)
                vr[m] = qkv[m * QKV_STRIDE + 2 * DIMC + h * HD + lane];
            #pragma unroll
            for (int i = 0; i < 24; i++) v2[i] = pack_pair(vr[2*i], vr[2*i+1]);
            v48 = vr[48];
        }

        const float* maskw = mask + (size_t)(b % nW) * NTOK * NTOK;
        float* O   = xT;                        // reuse as O_T [256][50]
        float* ps0 = ps + h * 104;
        float* ps1 = ps0 + 52;

        auto score_row = [&](int n, float* psh) {
            float sA = 0.0f, sB = 0.0f;
            const float4* q4 = (const float4*)(qkv + n * QKV_STRIDE + h * HD);
            #pragma unroll
            for (int i = 0; i < 8; i++) {
                float4 t = q4[i];
                sA = fmaf(t.x, kA[4*i+0], sA); sB = fmaf(t.x, kB[4*i+0], sB);
                sA = fmaf(t.y, kA[4*i+1], sA); sB = fmaf(t.y, kB[4*i+1], sB);
                sA = fmaf(t.z, kA[4*i+2], sA); sB = fmaf(t.z, kB[4*i+2], sB);
                sA = fmaf(t.w, kA[4*i+3], sA); sB = fmaf(t.w, kB[4*i+3], sB);
            }
            {
                int ri = __ldg(rel_index + n * NTOK + lane);
                sA += __ldg(bias_table + ri * NH + h) + __ldg(maskw + n * NTOK + lane);
            }
            if (lane < 17) {
                int rj = __ldg(rel_index + n * NTOK + 32 + lane);
                sB += __ldg(bias_table + rj * NH + h) + __ldg(maskw + n * NTOK + 32 + lane);
            }
            float mx = (lane < 17) ? fmaxf(sA, sB) : sA;
            #pragma unroll
            for (int o = 16; o > 0; o >>= 1)
                mx = fmaxf(mx, __shfl_xor_sync(0xffffffffu, mx, o));
            float eA = __expf(sA - mx);
            float eB = (lane < 17) ? __expf(sB - mx) : 0.0f;
            float sm = eA + eB;
            #pragma unroll
            for (int o = 16; o > 0; o >>= 1)
                sm += __shfl_xor_sync(0xffffffffu, sm, o);
            float r = 1.0f / sm;
            psh[lane] = eA * r;
            if (lane < 17) psh[32 + lane] = eB * r;
        };

        auto pv_row = [&](const float* psh) -> float {
            u64 acc = 0ull;
            const u64* p2 = (const u64*)psh;
            #pragma unroll
            for (int i = 0; i < 24; i++) fma2(acc, p2[i], v2[i]);
            float lo, hi; unpack2(acc, lo, hi);
            return lo + hi + psh[48] * v48;
        };

        const int orow = (h * HD + lane) * XT_STRIDE;
        #pragma unroll 1
        for (int nb = 0; nb < NTOK - 1; nb += 2) {
            score_row(nb,     ps0);
            score_row(nb + 1, ps1);
            __syncwarp();
            float oA = pv_row(ps0);
            float oB = pv_row(ps1);
            O[orow + nb]     = oA;
            O[orow + nb + 1] = oB;
            __syncwarp();
        }
        score_row(48, ps0);
        __syncwarp();
        O[orow + 48] = pv_row(ps0);
    }
    __syncthreads();

    // ---- Phase 4: proj GEMM, 4 cols/thread x row-quarters ----
    {
        const int cg = tid & 63;
        const int rq = tid >> 6;
        float* ob = out + (size_t)b * NTOK * DIMC;
        const float* O = xT;   // [256][50], col 49 zero
        if      (rq == 0) proj_part<0, 7>(O, proj_w, proj_b, ob, cg);
        else if (rq == 1) proj_part<7, 6>(O, proj_w, proj_b, ob, cg);
        else if (rq == 2) proj_part<13, 6>(O, proj_w, proj_b, ob, cg);
        else              proj_part<19, 6>(O, proj_w, proj_b, ob, cg);
    }
}

extern "C" void kernel_launch(void* const* d_in, const int* in_sizes, int n_in,
                              void* d_out, int out_size) {
    const float* x          = (const float*)d_in[0];
    const float* mask       = (const float*)d_in[1];
    const float* qkv_w      = (const float*)d_in[2];
    const float* qkv_b      = (const float*)d_in[3];
    const float* proj_w     = (const float*)d_in[4];
    const float* proj_b     = (const float*)d_in[5];
    const float* bias_table = (const float*)d_in[6];
    const int*   rel_index  = (const int*)d_in[7];
    float* out = (float*)d_out;

    const int B  = in_sizes[0] / (NTOK * DIMC);     // 2048
    const int nW = in_sizes[1] / (NTOK * NTOK);     // 64

    cudaFuncSetAttribute(win_attn_fused_kernel,
                         cudaFuncAttributeMaxDynamicSharedMemorySize, SM_BYTES);
    win_attn_fused_kernel<<<B, 256, SM_BYTES>>>(
        x, mask, qkv_w, qkv_b, proj_w, proj_b, bias_table, rel_index, out, nW);
}

// round 4
// speedup vs baseline: 1.0822x; 1.0285x over previous
#include <cuda_runtime.h>
#include <cuda_bf16.h>

#define NTOK 49
#define DIMC 256
#define NH   8
#define HD   32
#define QKV_STRIDE 772     // 768 + 4 pad
#define XT_STRIDE  50      // 49 + zero pad row
#define ATT_SCALE 0.17677669529663687f   // 32^-0.5

// smem layout (floats):
//   xT  [256][50]    @ 0        (reused as O_T [256][50] after attention)
//   qkv [49][772]    @ 12800
//   ps  [16][2][52]  @ 50628    (per-warp double softmax rows)
#define SM_XT   0
#define SM_QKV  12800
#define SM_PS   50628
#define SM_FLOATS (SM_PS + 16*104)         // 52292
#define SM_BYTES  (SM_FLOATS * 4)          // 209168

typedef unsigned long long u64;

__device__ __forceinline__ u64 pack2(float v) {
    u64 r; unsigned u = __float_as_uint(v);
    asm("mov.b64 %0, {%1, %1};" : "=l"(r) : "r"(u));
    return r;
}
__device__ __forceinline__ u64 pack_pair(float lo, float hi) {
    u64 r;
    asm("mov.b64 %0, {%1, %2};" : "=l"(r)
        : "r"(__float_as_uint(lo)), "r"(__float_as_uint(hi)));
    return r;
}
__device__ __forceinline__ void fma2(u64& acc, u64 a, u64 b) {
    asm("fma.rn.f32x2 %0, %1, %2, %3;" : "=l"(acc) : "l"(a), "l"(b), "l"(acc));
}
__device__ __forceinline__ void unpack2(u64 v, float& lo, float& hi) {
    unsigned a, b;
    asm("mov.b64 {%0, %1}, %2;" : "=r"(a), "=r"(b) : "l"(v));
    lo = __uint_as_float(a); hi = __uint_as_float(b);
}

// ---- QKV partial: NP row-pairs from pair I0, 3 cols (j, j+256, j+512) ----
template<int I0, int NP>
__device__ __forceinline__ void qkv_part(
    const float* __restrict__ xT, const float* __restrict__ qkv_w,
    const float* __restrict__ qkv_b, float* __restrict__ qkv, int j)
{
    u64 a0[NP], a1[NP], a2[NP];
    #pragma unroll
    for (int i = 0; i < NP; i++) { a0[i] = 0ull; a1[i] = 0ull; a2[i] = 0ull; }

    const int j1 = j + 256, j2 = j + 512;
    float c0 = __ldg(qkv_w + j), c1 = __ldg(qkv_w + j1), c2 = __ldg(qkv_w + j2);
    #pragma unroll 1
    for (int k = 0; k < DIMC; k++) {
        int kn = (k + 1 < DIMC) ? (k + 1) : (DIMC - 1);
        const float* wr = qkv_w + kn * 768;
        float n0 = __ldg(wr + j), n1 = __ldg(wr + j1), n2 = __ldg(wr + j2);
        u64 w0 = pack2(c0), w1 = pack2(c1), w2 = pack2(c2);
        const u64* xr = (const u64*)(xT + k * XT_STRIDE) + I0;
        #pragma unroll
        for (int i = 0; i < NP; i++) {
            u64 xv = xr[i];
            fma2(a0[i], xv, w0);
            fma2(a1[i], xv, w1);
            fma2(a2[i], xv, w2);
        }
        c0 = n0; c1 = n1; c2 = n2;
    }
    float b0 = __ldg(qkv_b + j), b1 = __ldg(qkv_b + j1), b2 = __ldg(qkv_b + j2);
    #pragma unroll
    for (int i = 0; i < NP; i++) {
        int row = 2 * (I0 + i);
        float lo, hi;
        unpack2(a0[i], lo, hi);
        qkv[row * QKV_STRIDE + j] = (lo + b0) * ATT_SCALE;
        if (row + 1 < NTOK) qkv[(row + 1) * QKV_STRIDE + j] = (hi + b0) * ATT_SCALE;
        unpack2(a1[i], lo, hi);
        qkv[row * QKV_STRIDE + j1] = lo + b1;
        if (row + 1 < NTOK) qkv[(row + 1) * QKV_STRIDE + j1] = hi + b1;
        unpack2(a2[i], lo, hi);
        qkv[row * QKV_STRIDE + j2] = lo + b2;
        if (row + 1 < NTOK) qkv[(row + 1) * QKV_STRIDE + j2] = hi + b2;
    }
}

// ---- Proj partial: NP row-pairs from pair I0, 2 cols (j, j+128) ----
template<int I0, int NP>
__device__ __forceinline__ void proj_part(
    const float* __restrict__ O, const float* __restrict__ proj_w,
    const float* __restrict__ proj_b, float* __restrict__ ob, int j)
{
    u64 a0[NP], a1[NP];
    #pragma unroll
    for (int i = 0; i < NP; i++) { a0[i] = 0ull; a1[i] = 0ull; }

    const int j1 = j + 128;
    float c0 = __ldg(proj_w + j), c1 = __ldg(proj_w + j1);
    #pragma unroll 1
    for (int k = 0; k < DIMC; k++) {
        int kn = (k + 1 < DIMC) ? (k + 1) : (DIMC - 1);
        const float* wr = proj_w + kn * DIMC;
        float n0 = __ldg(wr + j), n1 = __ldg(wr + j1);
        u64 w0 = pack2(c0), w1 = pack2(c1);
        const u64* orow = (const u64*)(O + k * XT_STRIDE) + I0;
        #pragma unroll
        for (int i = 0; i < NP; i++) {
            u64 ov = orow[i];
            fma2(a0[i], ov, w0);
            fma2(a1[i], ov, w1);
        }
        c0 = n0; c1 = n1;
    }
    float b0 = __ldg(proj_b + j), b1 = __ldg(proj_b + j1);
    #pragma unroll
    for (int i = 0; i < NP; i++) {
        int row = 2 * (I0 + i);
        float lo, hi;
        unpack2(a0[i], lo, hi);
        ob[row * DIMC + j] = lo + b0;
        if (row + 1 < NTOK) ob[(row + 1) * DIMC + j] = hi + b0;
        unpack2(a1[i], lo, hi);
        ob[row * DIMC + j1] = lo + b1;
        if (row + 1 < NTOK) ob[(row + 1) * DIMC + j1] = hi + b1;
    }
}

__global__ __launch_bounds__(512, 1)
void win_attn_fused_kernel(
    const float* __restrict__ x,          // [B, 49, 256]
    const float* __restrict__ mask,       // [nW, 49, 49]
    const float* __restrict__ qkv_w,      // [256, 768]
    const float* __restrict__ qkv_b,      // [768]
    const float* __restrict__ proj_w,     // [256, 256]
    const float* __restrict__ proj_b,     // [256]
    const float* __restrict__ bias_table, // [169, 8]
    const int*   __restrict__ rel_index,  // [49, 49]
    float*       __restrict__ out,        // [B, 49, 256]
    int nW)
{
    extern __shared__ float smem[];
    float* xT  = smem + SM_XT;    // [256][50]
    float* qkv = smem + SM_QKV;   // [49][772]
    float* ps  = smem + SM_PS;    // [16][2][52]

    const int b   = blockIdx.x;
    const int tid = threadIdx.x;

    // ---- Phase 1: load x transposed, zero pad row ----
    const float* xb = x + (size_t)b * NTOK * DIMC;
    for (int idx = tid; idx < NTOK * DIMC; idx += 512) {
        int n = idx >> 8;
        int k = idx & 255;
        xT[k * XT_STRIDE + n] = xb[idx];
    }
    if (tid < DIMC) xT[tid * XT_STRIDE + 49] = 0.0f;
    __syncthreads();

    // ---- Phase 2: QKV GEMM: 2 row-groups x 256 cols, 3 cols/thread ----
    {
        const int j  = tid & 255;
        const int rg = tid >> 8;
        if (rg == 0) qkv_part<0, 13>(xT, qkv_w, qkv_b, qkv, j);
        else         qkv_part<13, 12>(xT, qkv_w, qkv_b, qkv, j);
    }
    __syncthreads();

    // ---- Phase 3: attention. 2 warps per head (even/odd rows). ----
    {
        const int wid  = tid >> 5;
        const int lane = tid & 31;
        const int h    = wid & 7;
        const int half = wid >> 3;       // 0: even rows, 1: odd rows

        float kA[HD], kB[HD];
        {
            const float4* kp = (const float4*)(qkv + lane * QKV_STRIDE + DIMC + h * HD);
            #pragma unroll
            for (int i = 0; i < 8; i++) {
                float4 t = kp[i];
                kA[4*i] = t.x; kA[4*i+1] = t.y; kA[4*i+2] = t.z; kA[4*i+3] = t.w;
            }
        }
        if (lane < 17) {
            const float4* kp = (const float4*)(qkv + (lane + 32) * QKV_STRIDE + DIMC + h * HD);
            #pragma unroll
            for (int i = 0; i < 8; i++) {
                float4 t = kp[i];
                kB[4*i] = t.x; kB[4*i+1] = t.y; kB[4*i+2] = t.z; kB[4*i+3] = t.w;
            }
        } else {
            #pragma unroll
            for (int i = 0; i < HD; i++) kB[i] = 0.0f;
        }
        // v fragment packed as token pairs: lane owns head-dim d=lane
        u64 v2[24]; float v48;
        {
            float vr[NTOK];
            #pragma unroll
            for (int m = 0; m < NTOK; m++)
                vr[m] = qkv[m * QKV_STRIDE + 2 * DIMC + h * HD + lane];
            #pragma unroll
            for (int i = 0; i < 24; i++) v2[i] = pack_pair(vr[2*i], vr[2*i+1]);
            v48 = vr[48];
        }

        const float* maskw = mask + (size_t)(b % nW) * NTOK * NTOK;
        float* O   = xT;                    // reuse as O_T [256][50]
        float* ps0 = ps + wid * 104;
        float* ps1 = ps0 + 52;

        auto score_row = [&](int n, float* psh) {
            float sA = 0.0f, sB = 0.0f;
            const float4* q4 = (const float4*)(qkv + n * QKV_STRIDE + h * HD);
            #pragma unroll
            for (int i = 0; i < 8; i++) {
                float4 t = q4[i];
                sA = fmaf(t.x, kA[4*i+0], sA); sB = fmaf(t.x, kB[4*i+0], sB);
                sA = fmaf(t.y, kA[4*i+1], sA); sB = fmaf(t.y, kB[4*i+1], sB);
                sA = fmaf(t.z, kA[4*i+2], sA); sB = fmaf(t.z, kB[4*i+2], sB);
                sA = fmaf(t.w, kA[4*i+3], sA); sB = fmaf(t.w, kB[4*i+3], sB);
            }
            {
                int ri = __ldg(rel_index + n * NTOK + lane);
                sA += __ldg(bias_table + ri * NH + h) + __ldg(maskw + n * NTOK + lane);
            }
            if (lane < 17) {
                int rj = __ldg(rel_index + n * NTOK + 32 + lane);
                sB += __ldg(bias_table + rj * NH + h) + __ldg(maskw + n * NTOK + 32 + lane);
            }
            float mx = (lane < 17) ? fmaxf(sA, sB) : sA;
            #pragma unroll
            for (int o = 16; o > 0; o >>= 1)
                mx = fmaxf(mx, __shfl_xor_sync(0xffffffffu, mx, o));
            float eA = __expf(sA - mx);
            float eB = (lane < 17) ? __expf(sB - mx) : 0.0f;
            float sm = eA + eB;
            #pragma unroll
            for (int o = 16; o > 0; o >>= 1)
                sm += __shfl_xor_sync(0xffffffffu, sm, o);
            float r = 1.0f / sm;
            psh[lane] = eA * r;
            if (lane < 17) psh[32 + lane] = eB * r;
        };

        auto pv_row = [&](const float* psh) -> float {
            u64 acc = 0ull;
            const u64* p2 = (const u64*)psh;
            #pragma unroll
            for (int i = 0; i < 24; i++) fma2(acc, p2[i], v2[i]);
            float lo, hi; unpack2(acc, lo, hi);
            return lo + hi + psh[48] * v48;
        };

        const int orow = (h * HD + lane) * XT_STRIDE;
        #pragma unroll 1
        for (int t = 0; t < 13; t++) {
            int n0 = half + 4 * t;
            int n1 = n0 + 2;
            if (n1 < NTOK) {
                score_row(n0, ps0);
                score_row(n1, ps1);
                __syncwarp();
                float oA = pv_row(ps0);
                float oB = pv_row(ps1);
                O[orow + n0] = oA;
                O[orow + n1] = oB;
                __syncwarp();
            } else if (n0 < NTOK) {
                score_row(n0, ps0);
                __syncwarp();
                O[orow + n0] = pv_row(ps0);
                __syncwarp();
            }
        }
    }
    __syncthreads();

    // ---- Phase 4: proj GEMM: 2 cols/thread x 4 row-groups ----
    {
        const int j  = tid & 127;
        const int rg = tid >> 7;
        float* ob = out + (size_t)b * NTOK * DIMC;
        const float* O = xT;   // [256][50], col 49 zero
        if      (rg == 0) proj_part<0, 7>(O, proj_w, proj_b, ob, j);
        else if (rg == 1) proj_part<7, 6>(O, proj_w, proj_b, ob, j);
        else if (rg == 2) proj_part<13, 6>(O, proj_w, proj_b, ob, j);
        else              proj_part<19, 6>(O, proj_w, proj_b, ob, j);
    }
}

extern "C" void kernel_launch(void* const* d_in, const int* in_sizes, int n_in,
                              void* d_out, int out_size) {
    const float* x          = (const float*)d_in[0];
    const float* mask       = (const float*)d_in[1];
    const float* qkv_w      = (const float*)d_in[2];
    const float* qkv_b      = (const float*)d_in[3];
    const float* proj_w     = (const float*)d_in[4];
    const float* proj_b     = (const float*)d_in[5];
    const float* bias_table = (const float*)d_in[6];
    const int*   rel_index  = (const int*)d_in[7];
    float* out = (float*)d_out;

    const int B  = in_sizes[0] / (NTOK * DIMC);     // 2048
    const int nW = in_sizes[1] / (NTOK * NTOK);     // 64

    cudaFuncSetAttribute(win_attn_fused_kernel,
                         cudaFuncAttributeMaxDynamicSharedMemorySize, SM_BYTES);
    win_attn_fused_kernel<<<B, 512, SM_BYTES>>>(
        x, mask, qkv_w, qkv_b, proj_w, proj_b, bias_table, rel_index, out, nW);
}

// round 6
// speedup vs baseline: 1.5809x; 1.4609x over previous
#include <cuda_runtime.h>
#include <cuda_bf16.h>
#include <cstdint>

#define NTOK 49
#define DIMC 256
#define NH   8
#define HD   32
#define ATT_SCALE 0.17677669529663687f   // 32^-0.5

#define TOKENS   100352                  // 2048 * 49
#define NTILES   784                     // TOKENS / 128
#define QKV_NC   24                      // 768 / 32
#define PROJ_NC  8                       // 256 / 32
#define CH_ELEMS 10240                   // 256 rows * 40 (32 data + 8 pad) bf16
#define CH_BYTES 20480

// ---------------- global scratch (static, no allocs) ----------------
__device__ __align__(128) float g_qkv[(size_t)TOKENS * 768];
__device__ __align__(128) float g_attn[(size_t)TOKENS * 256];
__device__ __align__(128) __nv_bfloat16 g_wq_hi[QKV_NC * CH_ELEMS];
__device__ __align__(128) __nv_bfloat16 g_wq_lo[QKV_NC * CH_ELEMS];
__device__ __align__(128) __nv_bfloat16 g_wp_hi[PROJ_NC * CH_ELEMS];
__device__ __align__(128) __nv_bfloat16 g_wp_lo[PROJ_NC * CH_ELEMS];

// ---------------- ptx helpers ----------------
__device__ __forceinline__ uint32_t smem_u32(const void* p) {
    uint32_t a;
    asm("{ .reg .u64 t; cvta.to.shared.u64 t, %1; cvt.u32.u64 %0, t; }"
        : "=r"(a) : "l"(p));
    return a;
}

#define MBAR_INIT(a, c) \
    asm volatile("mbarrier.init.shared.b64 [%0], %1;" :: "r"(a), "r"(c) : "memory")
#define MBAR_EXPECT_TX(a, b) \
    asm volatile("mbarrier.arrive.expect_tx.shared.b64 _, [%0], %1;" :: "r"(a), "r"(b) : "memory")
#define MBAR_WAIT(a, ph) do { \
    uint32_t _m = (a); uint32_t _p = (ph); uint32_t _d; \
    asm volatile("{\n\t.reg .pred p;\n\t" \
        "mbarrier.try_wait.parity.acquire.cta.shared::cta.b64 p, [%1], %2;\n\t" \
        "selp.b32 %0, 1, 0, p;\n\t}" : "=r"(_d) : "r"(_m), "r"(_p) : "memory"); \
    if (!_d) { \
        asm volatile("{\n\t.reg .pred P1;\n\tWL_%=:\n\t" \
            "mbarrier.try_wait.parity.acquire.cta.shared::cta.b64 P1, [%0], %1, 0x989680;\n\t" \
            "@P1 bra.uni WD_%=;\n\tbra.uni WL_%=;\n\tWD_%=:\n\t}" \
            :: "r"(_m), "r"(_p) : "memory"); \
    } } while (0)

#define BULK_G2S(dst, src, bytes, mbar) \
    asm volatile("cp.async.bulk.shared::cluster.global.mbarrier::complete_tx::bytes " \
                 "[%0], [%1], %2, [%3];" \
                 :: "r"(dst), "l"(src), "r"(bytes), "r"(mbar) : "memory")

#define LDSM_X4(r, addr) \
    asm volatile("ldmatrix.sync.aligned.m8n8.x4.shared.b16 {%0,%1,%2,%3}, [%4];" \
        : "=r"((r)[0]), "=r"((r)[1]), "=r"((r)[2]), "=r"((r)[3]) : "r"(addr))

#define LDSM_X2T(r, addr) \
    asm volatile("ldmatrix.sync.aligned.m8n8.x2.trans.shared.b16 {%0,%1}, [%2];" \
        : "=r"((r)[0]), "=r"((r)[1]) : "r"(addr))

#define MMA16816(c, a, b) \
    asm volatile("mma.sync.aligned.m16n8k16.row.col.f32.bf16.bf16.f32 " \
        "{%0,%1,%2,%3}, {%4,%5,%6,%7}, {%8,%9}, {%0,%1,%2,%3};" \
        : "+f"((c)[0]), "+f"((c)[1]), "+f"((c)[2]), "+f"((c)[3]) \
        : "r"((a)[0]), "r"((a)[1]), "r"((a)[2]), "r"((a)[3]), \
          "r"((b)[0]), "r"((b)[1]))

// ---------------- kernel 1: weight prep ----------------
// Splits W (fp32, [K=256][ncols]) into bf16 hi/lo, rearranged per 32-col chunk
// as 256 rows x 80B (32 bf16 data + 16B pad) -> one contiguous 20480B block
// per chunk per term, ready for a single cp.async.bulk.
__global__ void prep_weights(const float* __restrict__ qkv_w,
                             const float* __restrict__ proj_w) {
    int c = blockIdx.x;                 // 0..31
    bool isq = c < QKV_NC;
    int chunk = isq ? c : c - QKV_NC;
    const float* W = isq ? qkv_w : proj_w;
    int ncols = isq ? 768 : 256;
    __nv_bfloat16* hi = (isq ? g_wq_hi : g_wp_hi) + chunk * CH_ELEMS;
    __nv_bfloat16* lo = (isq ? g_wq_lo : g_wp_lo) + chunk * CH_ELEMS;
    for (int idx = threadIdx.x; idx < CH_ELEMS; idx += blockDim.x) {
        int k = idx / 40;
        int n = idx - k * 40;
        float w = (n < 32) ? __ldg(W + k * ncols + chunk * 32 + n) : 0.0f;
        __nv_bfloat16 h = __float2bfloat16(w);
        __nv_bfloat16 l = __float2bfloat16(w - __bfloat162float(h));
        hi[idx] = h;
        lo[idx] = l;
    }
}

// ---------------- kernel 2/4: flat split-bf16 GEMM via mma.sync ----------------
// which==0: QKV  (A=x [tok,256], dst=g_qkv [tok,768], 24 chunks, q cols scaled)
// which==1: proj (A=g_attn,      dst=out   [tok,256],  8 chunks)
//
// smem: A_hi [128][272 bf16] (544B rows) @0, A_lo @69632,
//       B bufs 2 x (hi,lo) x 20480B @139264, mbarriers @221184.
#define SA_HI 0
#define SA_LO 69632
#define SB    139264
#define SMB   221184
#define GEMM_SMEM 221248

__global__ __launch_bounds__(256, 1)
void gemm_hmma(const float* __restrict__ x, const float* __restrict__ bias,
               float* __restrict__ out, int which) {
    extern __shared__ __align__(128) char smem[];
    const uint32_t sb = smem_u32(smem);
    const int tid = threadIdx.x, wid = tid >> 5, lane = tid & 31;

    const int nc = which ? PROJ_NC : QKV_NC;
    const __nv_bfloat16* Whi = which ? g_wp_hi : g_wq_hi;
    const __nv_bfloat16* Wlo = which ? g_wp_lo : g_wq_lo;
    const float* A_src = which ? g_attn : x;
    float* dst = which ? out : g_qkv;
    const int dstride = which ? 256 : 768;

    // mbarriers + first two B chunk loads
    if (tid == 0) {
        MBAR_INIT(sb + SMB, 1);
        MBAR_INIT(sb + SMB + 8, 1);
        #pragma unroll
        for (int i = 0; i < 2 && i < nc; i++) {
            uint32_t mb = sb + SMB + i * 8;
            MBAR_EXPECT_TX(mb, 2 * CH_BYTES);
            uint32_t d = sb + SB + i * (2 * CH_BYTES);
            BULK_G2S(d,            (const void*)(Whi + i * CH_ELEMS), CH_BYTES, mb);
            BULK_G2S(d + CH_BYTES, (const void*)(Wlo + i * CH_ELEMS), CH_BYTES, mb);
        }
    }

    // A tile: 128x256 fp32 -> bf16 hi/lo into 544B-stride smem rows
    {
        const float4* a4 = (const float4*)(A_src + (size_t)blockIdx.x * 128 * 256);
        #pragma unroll 4
        for (int it = 0; it < 32; it++) {
            int e = it * 256 + tid;          // float4 index
            int row = e >> 6;
            int k4 = (e & 63) * 4;
            float4 v = __ldg(a4 + e);
            __nv_bfloat16 h0 = __float2bfloat16(v.x);
            __nv_bfloat16 h1 = __float2bfloat16(v.y);
            __nv_bfloat16 h2 = __float2bfloat16(v.z);
            __nv_bfloat16 h3 = __float2bfloat16(v.w);
            __nv_bfloat16 l0 = __float2bfloat16(v.x - __bfloat162float(h0));
            __nv_bfloat16 l1 = __float2bfloat16(v.y - __bfloat162float(h1));
            __nv_bfloat16 l2 = __float2bfloat16(v.z - __bfloat162float(h2));
            __nv_bfloat16 l3 = __float2bfloat16(v.w - __bfloat162float(h3));
            uint32_t off = (uint32_t)row * 544 + (uint32_t)k4 * 2;
            uint2 hv, lv;
            hv.x = ((uint32_t)__bfloat16_as_ushort(h1) << 16) | __bfloat16_as_ushort(h0);
            hv.y = ((uint32_t)__bfloat16_as_ushort(h3) << 16) | __bfloat16_as_ushort(h2);
            lv.x = ((uint32_t)__bfloat16_as_ushort(l1) << 16) | __bfloat16_as_ushort(l0);
            lv.y = ((uint32_t)__bfloat16_as_ushort(l3) << 16) | __bfloat16_as_ushort(l2);
            *(uint2*)(smem + SA_HI + off) = hv;
            *(uint2*)(smem + SA_LO + off) = lv;
        }
    }
    __syncthreads();

    // warp tiling: 4m x 2n; warp tile m32 x n16
    const int warp_m = wid & 3, warp_n = wid >> 2;
    const int m0 = warp_m * 32, n0 = warp_n * 16;
    const int lr = lane & 15, lc = lane >> 4;
    // ldmatrix.x4 A address: row = m0 + mf*16 + lr, kcol = ks*16 + lc*8
    const uint32_t a_off = sb + (uint32_t)(m0 + lr) * 544 + (uint32_t)lc * 16;
    // ldmatrix.x2.trans B address (lanes 0-15): row k = ks*16 + lr, col n0 + nf*8
    const uint32_t b_off = (uint32_t)lr * 80 + (uint32_t)n0 * 2;

    const size_t row_base = (size_t)blockIdx.x * 128;

    for (int c = 0; c < nc; c++) {
        const int buf = c & 1;
        MBAR_WAIT(sb + SMB + buf * 8, (c >> 1) & 1);
        const uint32_t Bb = sb + SB + buf * (2 * CH_BYTES) + b_off;

        float acc[2][2][4];
        #pragma unroll
        for (int mf = 0; mf < 2; mf++)
            #pragma unroll
            for (int nf = 0; nf < 2; nf++)
                #pragma unroll
                for (int i = 0; i < 4; i++) acc[mf][nf][i] = 0.0f;

        #pragma unroll 4
        for (int ks = 0; ks < 16; ks++) {
            uint32_t ah[2][4], al[2][4], bh[2][2], bl[2][2];
            #pragma unroll
            for (int mf = 0; mf < 2; mf++) {
                uint32_t aa = a_off + (uint32_t)mf * (16 * 544) + (uint32_t)ks * 32;
                LDSM_X4(ah[mf], aa + SA_HI);
                LDSM_X4(al[mf], aa + SA_LO);
            }
            #pragma unroll
            for (int nf = 0; nf < 2; nf++) {
                uint32_t ba = Bb + (uint32_t)ks * (16 * 80) + (uint32_t)nf * 16;
                LDSM_X2T(bh[nf], ba);
                LDSM_X2T(bl[nf], ba + CH_BYTES);
            }
            #pragma unroll
            for (int mf = 0; mf < 2; mf++)
                #pragma unroll
                for (int nf = 0; nf < 2; nf++) {
                    MMA16816(acc[mf][nf], ah[mf], bh[nf]);
                    MMA16816(acc[mf][nf], al[mf], bh[nf]);
                    MMA16816(acc[mf][nf], ah[mf], bl[nf]);
                }
        }

        // epilogue: bias (+ATT_SCALE on q columns), store fp32 to dst
        const float sc = (!which && c < 8) ? ATT_SCALE : 1.0f;
        const int colb = c * 32 + n0 + 2 * (lane & 3);
        const size_t rowb = row_base + m0 + (lane >> 2);
        #pragma unroll
        for (int mf = 0; mf < 2; mf++) {
            #pragma unroll
            for (int nf = 0; nf < 2; nf++) {
                int cc = colb + nf * 8;
                float b0 = __ldg(bias + cc), b1 = __ldg(bias + cc + 1);
                size_t r0 = rowb + mf * 16;
                float2 o0 = make_float2((acc[mf][nf][0] + b0) * sc,
                                        (acc[mf][nf][1] + b1) * sc);
                float2 o1 = make_float2((acc[mf][nf][2] + b0) * sc,
                                        (acc[mf][nf][3] + b1) * sc);
                *(float2*)(dst + r0 * dstride + cc) = o0;
                *(float2*)(dst + (r0 + 8) * dstride + cc) = o1;
            }
        }
        __syncthreads();
        if (tid == 0 && c + 2 < nc) {
            uint32_t mb = sb + SMB + buf * 8;
            MBAR_EXPECT_TX(mb, 2 * CH_BYTES);
            uint32_t d = sb + SB + buf * (2 * CH_BYTES);
            BULK_G2S(d,            (const void*)(Whi + (c + 2) * CH_ELEMS), CH_BYTES, mb);
            BULK_G2S(d + CH_BYTES, (const void*)(Wlo + (c + 2) * CH_ELEMS), CH_BYTES, mb);
        }
    }
}

// ---------------- kernel 3: attention (proven round-4 logic) ----------------
typedef unsigned long long u64;
__device__ __forceinline__ u64 pack_pair(float lo, float hi) {
    u64 r;
    asm("mov.b64 %0, {%1, %2};" : "=l"(r)
        : "r"(__float_as_uint(lo)), "r"(__float_as_uint(hi)));
    return r;
}
__device__ __forceinline__ void fma2(u64& acc, u64 a, u64 b) {
    asm("fma.rn.f32x2 %0, %1, %2, %3;" : "=l"(acc) : "l"(a), "l"(b), "l"(acc));
}
__device__ __forceinline__ void unpack2(u64 v, float& lo, float& hi) {
    unsigned a, b;
    asm("mov.b64 {%0, %1}, %2;" : "=r"(a), "=r"(b) : "l"(v));
    lo = __uint_as_float(a); hi = __uint_as_float(b);
}

__global__ __launch_bounds__(512, 1)
void attn_kernel(const float* __restrict__ mask,
                 const float* __restrict__ bias_table,
                 const int* __restrict__ rel_index, int nW) {
    __shared__ float ps[16 * 104];

    const int b    = blockIdx.x;
    const int tid  = threadIdx.x;
    const int wid  = tid >> 5;
    const int lane = tid & 31;
    const int h    = wid & 7;
    const int hf   = wid >> 3;
    const size_t base = (size_t)b * NTOK;

    const float* qg = g_qkv + base * 768;     // q (pre-scaled), k, v interleaved
    const float* kg = qg + 256;
    const float* vg = qg + 512;

    float kA[HD], kB[HD];
    {
        const float4* kp = (const float4*)(kg + (size_t)lane * 768 + h * HD);
        #pragma unroll
        for (int i = 0; i < 8; i++) {
            float4 t = __ldg(kp + i);
            kA[4*i] = t.x; kA[4*i+1] = t.y; kA[4*i+2] = t.z; kA[4*i+3] = t.w;
        }
    }
    if (lane < 17) {
        const float4* kp = (const float4*)(kg + (size_t)(lane + 32) * 768 + h * HD);
        #pragma unroll
        for (int i = 0; i < 8; i++) {
            float4 t = __ldg(kp + i);
            kB[4*i] = t.x; kB[4*i+1] = t.y; kB[4*i+2] = t.z; kB[4*i+3] = t.w;
        }
    } else {
        #pragma unroll
        for (int i = 0; i < HD; i++) kB[i] = 0.0f;
    }
    u64 v2[24]; float v48;
    {
        float vr[NTOK];
        #pragma unroll
        for (int m = 0; m < NTOK; m++)
            vr[m] = __ldg(vg + (size_t)m * 768 + h * HD + lane);
        #pragma unroll
        for (int i = 0; i < 24; i++) v2[i] = pack_pair(vr[2*i], vr[2*i+1]);
        v48 = vr[48];
    }

    const float* maskw = mask + (size_t)(b % nW) * NTOK * NTOK;
    float* ps0 = ps + wid * 104;
    float* ps1 = ps0 + 52;
    float* Og  = g_attn + base * 256 + h * HD + lane;

    auto score_row = [&](int n, float* psh) {
        float sA = 0.0f, sB = 0.0f;
        const float4* q4 = (const float4*)(qg + (size_t)n * 768 + h * HD);
        #pragma unroll
        for (int i = 0; i < 8; i++) {
            float4 t = __ldg(q4 + i);
            sA = fmaf(t.x, kA[4*i+0], sA); sB = fmaf(t.x, kB[4*i+0], sB);
            sA = fmaf(t.y, kA[4*i+1], sA); sB = fmaf(t.y, kB[4*i+1], sB);
            sA = fmaf(t.z, kA[4*i+2], sA); sB = fmaf(t.z, kB[4*i+2], sB);
            sA = fmaf(t.w, kA[4*i+3], sA); sB = fmaf(t.w, kB[4*i+3], sB);
        }
        {
            int ri = __ldg(rel_index + n * NTOK + lane);
            sA += __ldg(bias_table + ri * NH + h) + __ldg(maskw + n * NTOK + lane);
        }
        if (lane < 17) {
            int rj = __ldg(rel_index + n * NTOK + 32 + lane);
            sB += __ldg(bias_table + rj * NH + h) + __ldg(maskw + n * NTOK + 32 + lane);
        }
        float mx = (lane < 17) ? fmaxf(sA, sB) : sA;
        #pragma unroll
        for (int o = 16; o > 0; o >>= 1)
            mx = fmaxf(mx, __shfl_xor_sync(0xffffffffu, mx, o));
        float eA = __expf(sA - mx);
        float eB = (lane < 17) ? __expf(sB - mx) : 0.0f;
        float sm = eA + eB;
        #pragma unroll
        for (int o = 16; o > 0; o >>= 1)
            sm += __shfl_xor_sync(0xffffffffu, sm, o);
        float r = 1.0f / sm;
        psh[lane] = eA * r;
        if (lane < 17) psh[32 + lane] = eB * r;
    };

    auto pv_row = [&](const float* psh) -> float {
        u64 acc = 0ull;
        const u64* p2 = (const u64*)psh;
        #pragma unroll
        for (int i = 0; i < 24; i++) fma2(acc, p2[i], v2[i]);
        float lo, hi; unpack2(acc, lo, hi);
        return lo + hi + psh[48] * v48;
    };

    #pragma unroll 1
    for (int t = 0; t < 13; t++) {
        int n0 = hf + 4 * t;
        int n1 = n0 + 2;
        if (n1 < NTOK) {
            score_row(n0, ps0);
            score_row(n1, ps1);
            __syncwarp();
            float oA = pv_row(ps0);
            float oB = pv_row(ps1);
            Og[(size_t)n0 * 256] = oA;
            Og[(size_t)n1 * 256] = oB;
            __syncwarp();
        } else if (n0 < NTOK) {
            score_row(n0, ps0);
            __syncwarp();
            Og[(size_t)n0 * 256] = pv_row(ps0);
            __syncwarp();
        }
    }
}

// ---------------- launch ----------------
extern "C" void kernel_launch(void* const* d_in, const int* in_sizes, int n_in,
                              void* d_out, int out_size) {
    const float* x          = (const float*)d_in[0];
    const float* mask       = (const float*)d_in[1];
    const float* qkv_w      = (const float*)d_in[2];
    const float* qkv_b      = (const float*)d_in[3];
    const float* proj_w     = (const float*)d_in[4];
    const float* proj_b     = (const float*)d_in[5];
    const float* bias_table = (const float*)d_in[6];
    const int*   rel_index  = (const int*)d_in[7];
    float* out = (float*)d_out;

    const int nW = in_sizes[1] / (NTOK * NTOK);     // 64

    cudaFuncSetAttribute(gemm_hmma,
                         cudaFuncAttributeMaxDynamicSharedMemorySize, GEMM_SMEM);

    prep_weights<<<QKV_NC + PROJ_NC, 256>>>(qkv_w, proj_w);
    gemm_hmma<<<NTILES, 256, GEMM_SMEM>>>(x, qkv_b, nullptr, 0);
    attn_kernel<<<2048, 512>>>(mask, bias_table, rel_index, nW);
    gemm_hmma<<<NTILES, 256, GEMM_SMEM>>>(nullptr, proj_b, out, 1);
}